// round 4
// baseline (speedup 1.0000x reference)
#include <cuda_runtime.h>

// Problem constants: T=1024, H=2048, F=768, E=64, K=8
#define T_TOK   1024
#define H_DIM   2048
#define F_DIM   768
#define F2_DIM  1536
#define NEXP    64
#define TOPK    8
#define NPAIR   (T_TOK * TOPK)      // 8192 (token, k) pairs
#define MAXTILES 128                // sum ceil(cnt_e/128) <= 64 + 8192/128 = 128
#define MAXROWS  (MAXTILES * 128)   // 16384 padded rows

// ---------------------------------------------------------------------------
// Scratch (device globals — allocation-free per harness rules)
// ---------------------------------------------------------------------------
__device__ int   g_cnt[NEXP];
__device__ int   g_tilebase[NEXP];
__device__ int   g_ntiles;
__device__ int   g_tile_expert[MAXTILES];
__device__ int   g_rowtok[MAXROWS];                       // token per padded row (-1 = pad)
__device__ int   g_slot[NPAIR];                           // padded row per (t,k) pair
__device__ float g_gu [(size_t)MAXROWS * F2_DIM];         // 100.7 MB
__device__ float g_act[(size_t)MAXROWS * F_DIM];          //  50.3 MB
__device__ float g_y2 [(size_t)MAXROWS * H_DIM];          // 134.2 MB

typedef unsigned long long ull;

__device__ __forceinline__ float2 upk2(ull v) {
    float2 r; asm("mov.b64 {%0, %1}, %2;" : "=f"(r.x), "=f"(r.y) : "l"(v)); return r;
}
__device__ __forceinline__ void fma2(ull& d, ull a, ull b) {
    asm("fma.rn.f32x2 %0, %1, %2, %0;" : "+l"(d) : "l"(a), "l"(b));
}

// ---------------------------------------------------------------------------
// Dispatch: deterministic counting sort of the 8192 pairs by expert.
// ---------------------------------------------------------------------------
__global__ void k_init() {
    int i = blockIdx.x * blockDim.x + threadIdx.x;
    if (i < MAXROWS) g_rowtok[i] = -1;
    if (i < NEXP)    g_cnt[i] = 0;
}

__global__ void k_count(const int* __restrict__ ids) {
    int p = blockIdx.x * blockDim.x + threadIdx.x;
    if (p < NPAIR) atomicAdd(&g_cnt[ids[p]], 1);
}

__global__ void k_scan() {   // single thread: 64 experts, trivial
    if (threadIdx.x != 0 || blockIdx.x != 0) return;
    int base = 0;
    for (int e = 0; e < NEXP; e++) {
        g_tilebase[e] = base;
        int nt = (g_cnt[e] + 127) >> 7;
        for (int i = 0; i < nt; i++) g_tile_expert[(base >> 7) + i] = e;
        base += nt << 7;
    }
    g_ntiles = base >> 7;
}

__global__ void k_scatter(const int* __restrict__ ids) {
    // one block (warp) per expert; stable order over pair index via ballot
    const int e = blockIdx.x;
    const int lane = threadIdx.x;
    int off = g_tilebase[e];
    for (int base = 0; base < NPAIR; base += 32) {
        int p = base + lane;                        // NPAIR % 32 == 0
        bool m = (ids[p] == e);
        unsigned mask = __ballot_sync(0xffffffffu, m);
        if (m) {
            int r = off + __popc(mask & ((1u << lane) - 1u));
            g_rowtok[r] = p >> 3;                   // token index
            g_slot[p] = r;
        }
        off += __popc(mask);
    }
}

// ---------------------------------------------------------------------------
// Grouped GEMM1: for each m-tile (one expert), gu = gather(hidden) @ w1[e]^T
//   A rows gathered via g_rowtok; B = w1[e] [1536 x 2048]; C -> g_gu
// 128x128 tile, BK=8, 256 threads, 8x8 micro-tile, f32x2 packed FMA.
// A smem stored as duplicated pairs so each a-operand is one LDS.64.
// ---------------------------------------------------------------------------
__global__ __launch_bounds__(256) void gemm1_kernel(const float* __restrict__ hidden,
                                                    const float* __restrict__ w1) {
    const int mt = blockIdx.y;
    if (mt >= g_ntiles) return;
    const int e  = g_tile_expert[mt];
    const int n0 = blockIdx.x * 128;
    const float* B = w1 + (size_t)e * F2_DIM * H_DIM;

    __shared__ float2 As[8][128];
    __shared__ float  Bs[8][132];

    const int tid  = threadIdx.x;
    const int lrow = tid >> 1;
    const int lseg = tid & 1;
    const int tx   = tid & 15;
    const int ty   = tid >> 4;

    const int tok  = g_rowtok[mt * 128 + lrow];
    const bool av  = tok >= 0;
    const float* Aptr = hidden + (size_t)(av ? tok : 0) * H_DIM + lseg * 4;
    const float* Bptr = B + (size_t)(n0 + lrow) * H_DIM + lseg * 4;

    ull acc[8][4];
#pragma unroll
    for (int i = 0; i < 8; i++)
#pragma unroll
        for (int j = 0; j < 4; j++) acc[i][j] = 0ull;

    const int KSTEPS = H_DIM / 8;
    const float4 z4 = make_float4(0.f, 0.f, 0.f, 0.f);
    float4 aR = av ? *(const float4*)Aptr : z4;
    float4 bR = *(const float4*)Bptr;

    for (int kt = 0; kt < KSTEPS; kt++) {
        __syncthreads();
        As[lseg * 4 + 0][lrow] = make_float2(aR.x, aR.x);
        As[lseg * 4 + 1][lrow] = make_float2(aR.y, aR.y);
        As[lseg * 4 + 2][lrow] = make_float2(aR.z, aR.z);
        As[lseg * 4 + 3][lrow] = make_float2(aR.w, aR.w);
        Bs[lseg * 4 + 0][lrow] = bR.x;
        Bs[lseg * 4 + 1][lrow] = bR.y;
        Bs[lseg * 4 + 2][lrow] = bR.z;
        Bs[lseg * 4 + 3][lrow] = bR.w;
        __syncthreads();
        if (kt + 1 < KSTEPS) {
            aR = av ? *(const float4*)(Aptr + (kt + 1) * 8) : z4;
            bR = *(const float4*)(Bptr + (kt + 1) * 8);
        }
#pragma unroll
        for (int kk = 0; kk < 8; kk++) {
            const ull* apv = (const ull*)&As[kk][ty * 8];
            const ull* bp  = (const ull*)&Bs[kk][tx * 8];
            ull b0 = bp[0], b1 = bp[1], b2 = bp[2], b3 = bp[3];
            ull ap[8];
#pragma unroll
            for (int i = 0; i < 8; i++) ap[i] = apv[i];
#pragma unroll
            for (int i = 0; i < 8; i++) {
                fma2(acc[i][0], ap[i], b0);
                fma2(acc[i][1], ap[i], b1);
                fma2(acc[i][2], ap[i], b2);
                fma2(acc[i][3], ap[i], b3);
            }
        }
    }

    float* Cp = g_gu + (size_t)(mt * 128 + ty * 8) * F2_DIM + n0 + tx * 8;
#pragma unroll
    for (int i = 0; i < 8; i++) {
        float2 p0 = upk2(acc[i][0]), p1 = upk2(acc[i][1]);
        float2 p2 = upk2(acc[i][2]), p3 = upk2(acc[i][3]);
        *(float4*)(Cp + 0) = make_float4(p0.x, p0.y, p1.x, p1.y);
        *(float4*)(Cp + 4) = make_float4(p2.x, p2.y, p3.x, p3.y);
        Cp += F2_DIM;
    }
}

// ---------------------------------------------------------------------------
// SiGLU: act[r][f] = silu(gu[r][f]) * gu[r][F+f]    (valid padded rows only)
// ---------------------------------------------------------------------------
__global__ void silu_kernel() {
    int idx = blockIdx.x * blockDim.x + threadIdx.x;
    int r = idx / F_DIM;
    int f = idx - r * F_DIM;
    if (r >= g_ntiles * 128) return;
    float g = g_gu[(size_t)r * F2_DIM + f];
    float u = g_gu[(size_t)r * F2_DIM + F_DIM + f];
    g_act[(size_t)r * F_DIM + f] = (g / (1.f + expf(-g))) * u;
}

// ---------------------------------------------------------------------------
// Grouped GEMM2: y2 = act @ w2[e]^T   (per m-tile expert), K=768, N=2048
// ---------------------------------------------------------------------------
__global__ __launch_bounds__(256) void gemm2_kernel(const float* __restrict__ w2) {
    const int mt = blockIdx.y;
    if (mt >= g_ntiles) return;
    const int e  = g_tile_expert[mt];
    const int n0 = blockIdx.x * 128;
    const float* B = w2 + (size_t)e * H_DIM * F_DIM;

    __shared__ float2 As[8][128];
    __shared__ float  Bs[8][132];

    const int tid  = threadIdx.x;
    const int lrow = tid >> 1;
    const int lseg = tid & 1;
    const int tx   = tid & 15;
    const int ty   = tid >> 4;

    const float* Aptr = g_act + (size_t)(mt * 128 + lrow) * F_DIM + lseg * 4;
    const float* Bptr = B + (size_t)(n0 + lrow) * F_DIM + lseg * 4;

    ull acc[8][4];
#pragma unroll
    for (int i = 0; i < 8; i++)
#pragma unroll
        for (int j = 0; j < 4; j++) acc[i][j] = 0ull;

    const int KSTEPS = F_DIM / 8;   // 96
    float4 aR = *(const float4*)Aptr;
    float4 bR = *(const float4*)Bptr;

    for (int kt = 0; kt < KSTEPS; kt++) {
        __syncthreads();
        As[lseg * 4 + 0][lrow] = make_float2(aR.x, aR.x);
        As[lseg * 4 + 1][lrow] = make_float2(aR.y, aR.y);
        As[lseg * 4 + 2][lrow] = make_float2(aR.z, aR.z);
        As[lseg * 4 + 3][lrow] = make_float2(aR.w, aR.w);
        Bs[lseg * 4 + 0][lrow] = bR.x;
        Bs[lseg * 4 + 1][lrow] = bR.y;
        Bs[lseg * 4 + 2][lrow] = bR.z;
        Bs[lseg * 4 + 3][lrow] = bR.w;
        __syncthreads();
        if (kt + 1 < KSTEPS) {
            aR = *(const float4*)(Aptr + (kt + 1) * 8);
            bR = *(const float4*)(Bptr + (kt + 1) * 8);
        }
#pragma unroll
        for (int kk = 0; kk < 8; kk++) {
            const ull* apv = (const ull*)&As[kk][ty * 8];
            const ull* bp  = (const ull*)&Bs[kk][tx * 8];
            ull b0 = bp[0], b1 = bp[1], b2 = bp[2], b3 = bp[3];
            ull ap[8];
#pragma unroll
            for (int i = 0; i < 8; i++) ap[i] = apv[i];
#pragma unroll
            for (int i = 0; i < 8; i++) {
                fma2(acc[i][0], ap[i], b0);
                fma2(acc[i][1], ap[i], b1);
                fma2(acc[i][2], ap[i], b2);
                fma2(acc[i][3], ap[i], b3);
            }
        }
    }

    float* Cp = g_y2 + (size_t)(mt * 128 + ty * 8) * H_DIM + n0 + tx * 8;
#pragma unroll
    for (int i = 0; i < 8; i++) {
        float2 p0 = upk2(acc[i][0]), p1 = upk2(acc[i][1]);
        float2 p2 = upk2(acc[i][2]), p3 = upk2(acc[i][3]);
        *(float4*)(Cp + 0) = make_float4(p0.x, p0.y, p1.x, p1.y);
        *(float4*)(Cp + 4) = make_float4(p2.x, p2.y, p3.x, p3.y);
        Cp += H_DIM;
    }
}

// ---------------------------------------------------------------------------
// Combine (deterministic): out[t][h] = sum_k tw[t,k] * y2[slot[t,k]][h]
// ---------------------------------------------------------------------------
__global__ void combine_kernel(const float* __restrict__ tw, float* __restrict__ out) {
    int idx = blockIdx.x * blockDim.x + threadIdx.x;   // over T*H/4
    int t  = idx / (H_DIM / 4);
    int hq = idx - t * (H_DIM / 4);
    if (t >= T_TOK) return;
    float4 acc = make_float4(0.f, 0.f, 0.f, 0.f);
#pragma unroll
    for (int k = 0; k < TOPK; k++) {
        int   s = g_slot[t * TOPK + k];
        float w = tw[t * TOPK + k];
        float4 v = *(const float4*)&g_y2[(size_t)s * H_DIM + hq * 4];
        acc.x += w * v.x; acc.y += w * v.y; acc.z += w * v.z; acc.w += w * v.w;
    }
    *(float4*)&out[(size_t)t * H_DIM + hq * 4] = acc;
}

// ---------------------------------------------------------------------------
extern "C" void kernel_launch(void* const* d_in, const int* in_sizes, int n_in,
                              void* d_out, int out_size) {
    const float* hidden = (const float*)d_in[0];   // [T, H]
    const float* tw     = (const float*)d_in[1];   // [T, K]
    const int*   ids    = (const int*)d_in[2];     // [T, K]
    const float* w1     = (const float*)d_in[3];   // [E, 2F, H]
    const float* w2     = (const float*)d_in[4];   // [E, H, F]
    float*       out    = (float*)d_out;           // [T, H]

    k_init<<<MAXROWS / 256, 256>>>();
    k_count<<<NPAIR / 256, 256>>>(ids);
    k_scan<<<1, 32>>>();
    k_scatter<<<NEXP, 32>>>(ids);

    gemm1_kernel<<<dim3(F2_DIM / 128, MAXTILES), 256>>>(hidden, w1);
    silu_kernel<<<(MAXROWS * F_DIM) / 256, 256>>>();
    gemm2_kernel<<<dim3(H_DIM / 128, MAXTILES), 256>>>(w2);
    combine_kernel<<<(T_TOK * H_DIM / 4 + 255) / 256, 256>>>(tw, out);
}

// round 8
// speedup vs baseline: 2.1288x; 2.1288x over previous
#include <cuda_runtime.h>
#include <cuda_bf16.h>
#include <cstdint>

// Problem constants: T=1024, H=2048, F=768, E=64, K=8
#define T_TOK   1024
#define H_DIM   2048
#define F_DIM   768
#define F2_DIM  1536
#define NEXP    64
#define TOPK    8
#define NPAIR   (T_TOK * TOPK)
#define MAXTILES 128
#define MAXROWS  (MAXTILES * 128)

// ---------------------------------------------------------------------------
// Device-global scratch (allocation-free per harness rules)
// ---------------------------------------------------------------------------
__device__ int   g_cnt[NEXP];
__device__ int   g_tilebase[NEXP];
__device__ int   g_ntiles;
__device__ int   g_tile_expert[MAXTILES];
__device__ int   g_rowtok[MAXROWS];
__device__ int   g_slot[NPAIR];

__device__ __align__(256) __nv_bfloat16 g_w1h[(size_t)NEXP * F2_DIM * H_DIM];
__device__ __align__(256) __nv_bfloat16 g_w1l[(size_t)NEXP * F2_DIM * H_DIM];
__device__ __align__(256) __nv_bfloat16 g_w2h[(size_t)NEXP * H_DIM * F_DIM];
__device__ __align__(256) __nv_bfloat16 g_w2l[(size_t)NEXP * H_DIM * F_DIM];
__device__ __align__(256) __nv_bfloat16 g_Ah [(size_t)MAXROWS * H_DIM];
__device__ __align__(256) __nv_bfloat16 g_Al [(size_t)MAXROWS * H_DIM];
__device__ __align__(256) __nv_bfloat16 g_acth[(size_t)MAXROWS * F_DIM];
__device__ __align__(256) __nv_bfloat16 g_actl[(size_t)MAXROWS * F_DIM];
__device__ __align__(256) float g_gu [(size_t)MAXROWS * F2_DIM];
__device__ __align__(256) float g_y2 [(size_t)MAXROWS * H_DIM];

// ---------------------------------------------------------------------------
// Portable PTX helpers (all sm_80/sm_90 features; no 'a'-suffix instructions)
// ---------------------------------------------------------------------------
__device__ __forceinline__ uint32_t smem_u32(const void* p) {
    uint32_t a;
    asm("{ .reg .u64 t; cvta.to.shared.u64 t, %1; cvt.u32.u64 %0, t; }" : "=r"(a) : "l"(p));
    return a;
}
#define CP_ASYNC16(dst_u32, src) \
    asm volatile("cp.async.cg.shared.global [%0], [%1], 16;" :: "r"(dst_u32), "l"(src))
#define CP_COMMIT() asm volatile("cp.async.commit_group;" ::: "memory")
#define CP_WAIT(n)  asm volatile("cp.async.wait_group %0;" :: "n"(n) : "memory")

#define LDSM4(r, addr) \
    asm volatile("ldmatrix.sync.aligned.m8n8.x4.shared.b16 {%0,%1,%2,%3}, [%4];" \
        : "=r"((r)[0]), "=r"((r)[1]), "=r"((r)[2]), "=r"((r)[3]) : "r"(addr))

#define MMA_BF16(d, a, b0v, b1v) \
    asm volatile("mma.sync.aligned.m16n8k16.row.col.f32.bf16.bf16.f32 " \
        "{%0,%1,%2,%3}, {%4,%5,%6,%7}, {%8,%9}, {%0,%1,%2,%3};" \
        : "+f"((d)[0]), "+f"((d)[1]), "+f"((d)[2]), "+f"((d)[3]) \
        : "r"((a)[0]), "r"((a)[1]), "r"((a)[2]), "r"((a)[3]), "r"(b0v), "r"(b1v))

// ---------------------------------------------------------------------------
// bf16 split helpers
// ---------------------------------------------------------------------------
__device__ __forceinline__ uint32_t pk(__nv_bfloat16 a, __nv_bfloat16 b) {
    __nv_bfloat162 t(a, b);
    return *reinterpret_cast<uint32_t*>(&t);
}
__device__ __forceinline__ void split4(float4 v, uint2& hi, uint2& lo) {
    __nv_bfloat16 h0 = __float2bfloat16(v.x), h1 = __float2bfloat16(v.y);
    __nv_bfloat16 h2 = __float2bfloat16(v.z), h3 = __float2bfloat16(v.w);
    __nv_bfloat16 l0 = __float2bfloat16(v.x - __bfloat162float(h0));
    __nv_bfloat16 l1 = __float2bfloat16(v.y - __bfloat162float(h1));
    __nv_bfloat16 l2 = __float2bfloat16(v.z - __bfloat162float(h2));
    __nv_bfloat16 l3 = __float2bfloat16(v.w - __bfloat162float(h3));
    hi = make_uint2(pk(h0, h1), pk(h2, h3));
    lo = make_uint2(pk(l0, l1), pk(l2, l3));
}

// ---------------------------------------------------------------------------
// Dispatch (counting sort, deterministic)
// ---------------------------------------------------------------------------
__global__ void k_init() {
    int i = blockIdx.x * blockDim.x + threadIdx.x;
    if (i < MAXROWS) g_rowtok[i] = -1;
    if (i < NEXP)    g_cnt[i] = 0;
}
__global__ void k_count(const int* __restrict__ ids) {
    int p = blockIdx.x * blockDim.x + threadIdx.x;
    if (p < NPAIR) atomicAdd(&g_cnt[ids[p]], 1);
}
__global__ void k_scan() {
    if (threadIdx.x != 0 || blockIdx.x != 0) return;
    int base = 0;
    for (int e = 0; e < NEXP; e++) {
        g_tilebase[e] = base;
        int nt = (g_cnt[e] + 127) >> 7;
        for (int i = 0; i < nt; i++) g_tile_expert[(base >> 7) + i] = e;
        base += nt << 7;
    }
    g_ntiles = base >> 7;
}
__global__ void k_scatter(const int* __restrict__ ids) {
    const int e = blockIdx.x, lane = threadIdx.x;
    int off = g_tilebase[e];
    for (int base = 0; base < NPAIR; base += 32) {
        int p = base + lane;
        bool m = (ids[p] == e);
        unsigned mask = __ballot_sync(0xffffffffu, m);
        if (m) {
            int r = off + __popc(mask & ((1u << lane) - 1u));
            g_rowtok[r] = p >> 3;
            g_slot[p] = r;
        }
        off += __popc(mask);
    }
}

// ---------------------------------------------------------------------------
// Weight split: fp32 -> (hi, lo) bf16, streaming
// ---------------------------------------------------------------------------
__global__ void k_split(const float4* __restrict__ src, uint2* __restrict__ hi,
                        uint2* __restrict__ lo, size_t n4) {
    size_t i = (size_t)blockIdx.x * blockDim.x + threadIdx.x;
    if (i >= n4) return;
    uint2 h, l;
    split4(src[i], h, l);
    hi[i] = h; lo[i] = l;
}

// ---------------------------------------------------------------------------
// Gather + split hidden rows into padded [MAXROWS, H] bf16 hi/lo
// ---------------------------------------------------------------------------
__global__ void k_prepA(const float* __restrict__ hidden) {
    int idx = blockIdx.x * blockDim.x + threadIdx.x;   // over MAXROWS * 512
    int r  = idx >> 9;
    int c4 = idx & 511;
    if (r >= g_ntiles * 128) return;
    int tok = g_rowtok[r];
    float4 v = (tok >= 0) ? ((const float4*)hidden)[(size_t)tok * 512 + c4]
                          : make_float4(0.f, 0.f, 0.f, 0.f);
    uint2 h, l;
    split4(v, h, l);
    ((uint2*)g_Ah)[(size_t)r * 512 + c4] = h;
    ((uint2*)g_Al)[(size_t)r * 512 + c4] = l;
}

// ---------------------------------------------------------------------------
// SiLU + split: act = silu(gate)*up -> bf16 hi/lo
// ---------------------------------------------------------------------------
__global__ void k_silu() {
    int idx = blockIdx.x * blockDim.x + threadIdx.x;   // over MAXROWS * 192
    int r  = idx / 192;
    int c4 = idx - r * 192;
    if (r >= g_ntiles * 128) return;
    const float4* gu = (const float4*)g_gu;
    float4 g = gu[(size_t)r * 384 + c4];
    float4 u = gu[(size_t)r * 384 + 192 + c4];
    float4 h;
    h.x = (g.x / (1.f + expf(-g.x))) * u.x;
    h.y = (g.y / (1.f + expf(-g.y))) * u.y;
    h.z = (g.z / (1.f + expf(-g.z))) * u.z;
    h.w = (g.w / (1.f + expf(-g.w))) * u.w;
    uint2 hh, ll;
    split4(h, hh, ll);
    ((uint2*)g_acth)[(size_t)r * 192 + c4] = hh;
    ((uint2*)g_actl)[(size_t)r * 192 + c4] = ll;
}

// ---------------------------------------------------------------------------
// HMMA grouped GEMM: C[128x128] tile = (Ah+Al) @ (Bh+Bl)^T  (3-term bf16x3)
//   256 threads = 8 warps (2m x 4n), warp tile 64x32, BK=32, cp.async x2 buf.
//   Smem rows padded to 80B -> ldmatrix conflict-free (8 rows cover 32 banks).
// ---------------------------------------------------------------------------
#define BUF_B   10240              // 128 rows * 80 bytes
#define STAGE_B (4 * BUF_B)        // Ah, Al, Bh, Bl
#define GEMM_SMEM (2 * STAGE_B)    // 81920

template<int NK>   // NK = K / 32
__global__ __launch_bounds__(256) void hmma_gemm(
    const __nv_bfloat16* __restrict__ Ah, const __nv_bfloat16* __restrict__ Al, int lda,
    const __nv_bfloat16* __restrict__ Bh, const __nv_bfloat16* __restrict__ Bl,
    size_t bstride, int ldb, float* __restrict__ C, int ldc)
{
    const int mt = blockIdx.y;
    if (mt >= g_ntiles) return;
    const int e  = g_tile_expert[mt];
    const int n0 = blockIdx.x * 128;

    extern __shared__ char smem[];
    const uint32_t sb = smem_u32(smem);
    const int tid  = threadIdx.x;
    const int wid  = tid >> 5, lane = tid & 31;
    const int wr   = wid >> 2;          // 0..1 (m)
    const int wn   = wid & 3;           // 0..3 (n)

    // loader mapping: thread -> (row, 2 chunks of 16B)
    const int lrow = tid >> 1;          // 0..127
    const int cc   = (tid & 1) * 2;     // chunk 0 or 2
    const __nv_bfloat16* pAh = Ah + (size_t)(mt * 128 + lrow) * lda + cc * 8;
    const __nv_bfloat16* pAl = Al + (size_t)(mt * 128 + lrow) * lda + cc * 8;
    const __nv_bfloat16* pBh = Bh + (size_t)e * bstride + (size_t)(n0 + lrow) * ldb + cc * 8;
    const __nv_bfloat16* pBl = Bl + (size_t)e * bstride + (size_t)(n0 + lrow) * ldb + cc * 8;
    const uint32_t dst0 = sb + (uint32_t)lrow * 80 + (uint32_t)cc * 16;

#define LOAD_STAGE(s, k0) do {                                                  \
    uint32_t _d = dst0 + (s) * STAGE_B;                                         \
    CP_ASYNC16(_d + 0 * BUF_B,      pAh + (k0));                                \
    CP_ASYNC16(_d + 0 * BUF_B + 16, pAh + (k0) + 8);                            \
    CP_ASYNC16(_d + 1 * BUF_B,      pAl + (k0));                                \
    CP_ASYNC16(_d + 1 * BUF_B + 16, pAl + (k0) + 8);                            \
    CP_ASYNC16(_d + 2 * BUF_B,      pBh + (k0));                                \
    CP_ASYNC16(_d + 2 * BUF_B + 16, pBh + (k0) + 8);                            \
    CP_ASYNC16(_d + 3 * BUF_B,      pBl + (k0));                                \
    CP_ASYNC16(_d + 3 * BUF_B + 16, pBl + (k0) + 8);                            \
    CP_COMMIT();                                                                \
} while (0)

    // ldmatrix lane offsets (within a 16x16 tile at its smem base)
    // A frag reg order: [m0-7,c0][m8-15,c0][m0-7,c1][m8-15,c1]
    const uint32_t aoff = (uint32_t)((((lane >> 3) & 1) * 8 + (lane & 7)) * 80 + (lane >> 4) * 16);
    // B frag reg order: [n0-7,c0][n0-7,c1][n8-15,c0][n8-15,c1]
    const uint32_t boff = (uint32_t)(((lane >> 4) * 8 + (lane & 7)) * 80 + ((lane >> 3) & 1) * 16);

    float acc[4][4][4];
#pragma unroll
    for (int i = 0; i < 4; i++)
#pragma unroll
        for (int j = 0; j < 4; j++)
#pragma unroll
            for (int q = 0; q < 4; q++) acc[i][j][q] = 0.f;

    LOAD_STAGE(0, 0);

    for (int kt = 0; kt < NK; kt++) {
        if (kt + 1 < NK) { LOAD_STAGE((kt + 1) & 1, (kt + 1) * 32); CP_WAIT(1); }
        else             { CP_WAIT(0); }
        __syncthreads();

        const uint32_t stg = sb + (kt & 1) * STAGE_B;
        const uint32_t bAh = stg,              bAl = stg + BUF_B;
        const uint32_t bBh = stg + 2 * BUF_B,  bBl = stg + 3 * BUF_B;

#pragma unroll
        for (int kk = 0; kk < 2; kk++) {
            const uint32_t ko = (uint32_t)kk * 32;   // 16 bf16 = 32 bytes
            uint32_t ah[4][4], al[4][4];
#pragma unroll
            for (int i = 0; i < 4; i++) {
                uint32_t ta = (uint32_t)(wr * 64 + i * 16) * 80 + ko;
                LDSM4(ah[i], bAh + ta + aoff);
                LDSM4(al[i], bAl + ta + aoff);
            }
            uint32_t bh[2][4], bl[2][4];
#pragma unroll
            for (int j = 0; j < 2; j++) {
                uint32_t tb = (uint32_t)(wn * 32 + j * 16) * 80 + ko;
                LDSM4(bh[j], bBh + tb + boff);
                LDSM4(bl[j], bBl + tb + boff);
            }
#pragma unroll
            for (int i = 0; i < 4; i++)
#pragma unroll
                for (int j = 0; j < 2; j++)
#pragma unroll
                    for (int s = 0; s < 2; s++) {
                        MMA_BF16(acc[i][j * 2 + s], ah[i], bh[j][2 * s], bh[j][2 * s + 1]);
                        MMA_BF16(acc[i][j * 2 + s], ah[i], bl[j][2 * s], bl[j][2 * s + 1]);
                        MMA_BF16(acc[i][j * 2 + s], al[i], bh[j][2 * s], bh[j][2 * s + 1]);
                    }
        }
        __syncthreads();
    }
#undef LOAD_STAGE

    // epilogue: d0,d1 -> (r, c), (r, c+1); d2,d3 -> (r+8, c..)
    const int r  = lane >> 2;
    const int c2 = (lane & 3) * 2;
#pragma unroll
    for (int i = 0; i < 4; i++)
#pragma unroll
        for (int j = 0; j < 2; j++)
#pragma unroll
            for (int s = 0; s < 2; s++) {
                float* p = C + (size_t)(mt * 128 + wr * 64 + i * 16 + r) * ldc
                             + n0 + wn * 32 + j * 16 + s * 8 + c2;
                p[0] = acc[i][j * 2 + s][0];
                p[1] = acc[i][j * 2 + s][1];
                float* p2 = p + 8 * ldc;
                p2[0] = acc[i][j * 2 + s][2];
                p2[1] = acc[i][j * 2 + s][3];
            }
}

// ---------------------------------------------------------------------------
// Combine: out[t][h] = sum_k tw[t,k] * y2[slot[t,k]][h]
// ---------------------------------------------------------------------------
__global__ void combine_kernel(const float* __restrict__ tw, float* __restrict__ out) {
    int idx = blockIdx.x * blockDim.x + threadIdx.x;
    int t  = idx / (H_DIM / 4);
    int hq = idx - t * (H_DIM / 4);
    if (t >= T_TOK) return;
    float4 acc = make_float4(0.f, 0.f, 0.f, 0.f);
#pragma unroll
    for (int k = 0; k < TOPK; k++) {
        int   s = g_slot[t * TOPK + k];
        float w = tw[t * TOPK + k];
        float4 v = *(const float4*)&g_y2[(size_t)s * H_DIM + hq * 4];
        acc.x += w * v.x; acc.y += w * v.y; acc.z += w * v.z; acc.w += w * v.w;
    }
    *(float4*)&out[(size_t)t * H_DIM + hq * 4] = acc;
}

// ---------------------------------------------------------------------------
extern "C" void kernel_launch(void* const* d_in, const int* in_sizes, int n_in,
                              void* d_out, int out_size) {
    const float* hidden = (const float*)d_in[0];
    const float* tw     = (const float*)d_in[1];
    const int*   ids    = (const int*)d_in[2];
    const float* w1     = (const float*)d_in[3];
    const float* w2     = (const float*)d_in[4];
    float*       out    = (float*)d_out;

    static void *p_w1h, *p_w1l, *p_w2h, *p_w2l, *p_Ah, *p_Al, *p_ah, *p_al, *p_gu, *p_y2;
    cudaGetSymbolAddress(&p_w1h, g_w1h);
    cudaGetSymbolAddress(&p_w1l, g_w1l);
    cudaGetSymbolAddress(&p_w2h, g_w2h);
    cudaGetSymbolAddress(&p_w2l, g_w2l);
    cudaGetSymbolAddress(&p_Ah, g_Ah);
    cudaGetSymbolAddress(&p_Al, g_Al);
    cudaGetSymbolAddress(&p_ah, g_acth);
    cudaGetSymbolAddress(&p_al, g_actl);
    cudaGetSymbolAddress(&p_gu, g_gu);
    cudaGetSymbolAddress(&p_y2, g_y2);

    cudaFuncSetAttribute(hmma_gemm<H_DIM / 32>, cudaFuncAttributeMaxDynamicSharedMemorySize, GEMM_SMEM);
    cudaFuncSetAttribute(hmma_gemm<F_DIM / 32>, cudaFuncAttributeMaxDynamicSharedMemorySize, GEMM_SMEM);

    // dispatch
    k_init<<<MAXROWS / 256, 256>>>();
    k_count<<<NPAIR / 256, 256>>>(ids);
    k_scan<<<1, 32>>>();
    k_scatter<<<NEXP, 32>>>(ids);

    // weight splits (streaming, memory-bound)
    {
        size_t n4 = (size_t)NEXP * F2_DIM * H_DIM / 4;
        k_split<<<(unsigned)((n4 + 255) / 256), 256>>>((const float4*)w1, (uint2*)p_w1h, (uint2*)p_w1l, n4);
    }
    {
        size_t n4 = (size_t)NEXP * H_DIM * F_DIM / 4;
        k_split<<<(unsigned)((n4 + 255) / 256), 256>>>((const float4*)w2, (uint2*)p_w2h, (uint2*)p_w2l, n4);
    }

    // gather + split activations
    k_prepA<<<MAXROWS * 512 / 256, 256>>>(hidden);

    // GEMM1: gu = A @ w1^T   (K = 2048)
    hmma_gemm<H_DIM / 32><<<dim3(F2_DIM / 128, MAXTILES), 256, GEMM_SMEM>>>(
        (const __nv_bfloat16*)p_Ah, (const __nv_bfloat16*)p_Al, H_DIM,
        (const __nv_bfloat16*)p_w1h, (const __nv_bfloat16*)p_w1l,
        (size_t)F2_DIM * H_DIM, H_DIM, (float*)p_gu, F2_DIM);

    // SiLU + split
    k_silu<<<MAXROWS * 192 / 256, 256>>>();

    // GEMM2: y2 = act @ w2^T  (K = 768)
    hmma_gemm<F_DIM / 32><<<dim3(H_DIM / 128, MAXTILES), 256, GEMM_SMEM>>>(
        (const __nv_bfloat16*)p_ah, (const __nv_bfloat16*)p_al, F_DIM,
        (const __nv_bfloat16*)p_w2h, (const __nv_bfloat16*)p_w2l,
        (size_t)H_DIM * F_DIM, F_DIM, (float*)p_y2, H_DIM);

    combine_kernel<<<(T_TOK * H_DIM / 4 + 255) / 256, 256>>>(tw, out);
}

// round 10
// speedup vs baseline: 2.2174x; 1.0416x over previous
#include <cuda_runtime.h>
#include <cuda_bf16.h>
#include <cstdint>

// Problem constants: T=1024, H=2048, F=768, E=64, K=8
#define T_TOK   1024
#define H_DIM   2048
#define F_DIM   768
#define F2_DIM  1536
#define NEXP    64
#define TOPK    8
#define NPAIR   (T_TOK * TOPK)
#define TS      64                   // m-tile rows (was 128)
#define MAXTILES 256                 // worst case: 64 + 8192/64 = 192
#define MAXROWS  16384

// ---------------------------------------------------------------------------
// Device-global scratch (allocation-free per harness rules)
// ---------------------------------------------------------------------------
__device__ int   g_cnt[NEXP];
__device__ int   g_tilebase[NEXP];
__device__ int   g_ntiles;
__device__ int   g_tile_expert[MAXTILES];
__device__ int   g_rowtok[MAXROWS];
__device__ int   g_slot[NPAIR];

__device__ __align__(256) __nv_bfloat16 g_w1h[(size_t)NEXP * F2_DIM * H_DIM];
__device__ __align__(256) __nv_bfloat16 g_w1l[(size_t)NEXP * F2_DIM * H_DIM];
__device__ __align__(256) __nv_bfloat16 g_w2h[(size_t)NEXP * H_DIM * F_DIM];
__device__ __align__(256) __nv_bfloat16 g_w2l[(size_t)NEXP * H_DIM * F_DIM];
__device__ __align__(256) __nv_bfloat16 g_Ah [(size_t)MAXROWS * H_DIM];
__device__ __align__(256) __nv_bfloat16 g_Al [(size_t)MAXROWS * H_DIM];
__device__ __align__(256) __nv_bfloat16 g_acth[(size_t)MAXROWS * F_DIM];
__device__ __align__(256) __nv_bfloat16 g_actl[(size_t)MAXROWS * F_DIM];
__device__ __align__(256) float g_gu [(size_t)MAXROWS * F2_DIM];
__device__ __align__(256) float g_y2 [(size_t)MAXROWS * H_DIM];

// ---------------------------------------------------------------------------
// Portable PTX helpers
// ---------------------------------------------------------------------------
__device__ __forceinline__ uint32_t smem_u32(const void* p) {
    uint32_t a;
    asm("{ .reg .u64 t; cvta.to.shared.u64 t, %1; cvt.u32.u64 %0, t; }" : "=r"(a) : "l"(p));
    return a;
}
#define CP_ASYNC16(dst_u32, src) \
    asm volatile("cp.async.cg.shared.global [%0], [%1], 16;" :: "r"(dst_u32), "l"(src))
#define CP_COMMIT() asm volatile("cp.async.commit_group;" ::: "memory")
#define CP_WAIT(n)  asm volatile("cp.async.wait_group %0;" :: "n"(n) : "memory")

#define LDSM4(r, addr) \
    asm volatile("ldmatrix.sync.aligned.m8n8.x4.shared.b16 {%0,%1,%2,%3}, [%4];" \
        : "=r"((r)[0]), "=r"((r)[1]), "=r"((r)[2]), "=r"((r)[3]) : "r"(addr))

#define MMA_BF16(d, a, b0v, b1v) \
    asm volatile("mma.sync.aligned.m16n8k16.row.col.f32.bf16.bf16.f32 " \
        "{%0,%1,%2,%3}, {%4,%5,%6,%7}, {%8,%9}, {%0,%1,%2,%3};" \
        : "+f"((d)[0]), "+f"((d)[1]), "+f"((d)[2]), "+f"((d)[3]) \
        : "r"((a)[0]), "r"((a)[1]), "r"((a)[2]), "r"((a)[3]), "r"(b0v), "r"(b1v))

// ---------------------------------------------------------------------------
// bf16 split helpers
// ---------------------------------------------------------------------------
__device__ __forceinline__ uint32_t pk(__nv_bfloat16 a, __nv_bfloat16 b) {
    __nv_bfloat162 t(a, b);
    return *reinterpret_cast<uint32_t*>(&t);
}
__device__ __forceinline__ void split4(float4 v, uint2& hi, uint2& lo) {
    __nv_bfloat16 h0 = __float2bfloat16(v.x), h1 = __float2bfloat16(v.y);
    __nv_bfloat16 h2 = __float2bfloat16(v.z), h3 = __float2bfloat16(v.w);
    __nv_bfloat16 l0 = __float2bfloat16(v.x - __bfloat162float(h0));
    __nv_bfloat16 l1 = __float2bfloat16(v.y - __bfloat162float(h1));
    __nv_bfloat16 l2 = __float2bfloat16(v.z - __bfloat162float(h2));
    __nv_bfloat16 l3 = __float2bfloat16(v.w - __bfloat162float(h3));
    hi = make_uint2(pk(h0, h1), pk(h2, h3));
    lo = make_uint2(pk(l0, l1), pk(l2, l3));
}

// ---------------------------------------------------------------------------
// Dispatch (counting sort, deterministic) — 64-row tiles
// ---------------------------------------------------------------------------
__global__ void k_init() {
    int i = blockIdx.x * blockDim.x + threadIdx.x;
    if (i < MAXROWS) g_rowtok[i] = -1;
    if (i < NEXP)    g_cnt[i] = 0;
}
__global__ void k_count(const int* __restrict__ ids) {
    int p = blockIdx.x * blockDim.x + threadIdx.x;
    if (p < NPAIR) atomicAdd(&g_cnt[ids[p]], 1);
}
__global__ void k_scan() {
    if (threadIdx.x != 0 || blockIdx.x != 0) return;
    int base = 0;
    for (int e = 0; e < NEXP; e++) {
        g_tilebase[e] = base;
        int nt = (g_cnt[e] + TS - 1) / TS;
        for (int i = 0; i < nt; i++) g_tile_expert[base / TS + i] = e;
        base += nt * TS;
    }
    g_ntiles = base / TS;
}
__global__ void k_scatter(const int* __restrict__ ids) {
    const int e = blockIdx.x, lane = threadIdx.x;
    int off = g_tilebase[e];
    for (int base = 0; base < NPAIR; base += 32) {
        int p = base + lane;
        bool m = (ids[p] == e);
        unsigned mask = __ballot_sync(0xffffffffu, m);
        if (m) {
            int r = off + __popc(mask & ((1u << lane) - 1u));
            g_rowtok[r] = p >> 3;
            g_slot[p] = r;
        }
        off += __popc(mask);
    }
}

// ---------------------------------------------------------------------------
// Weight split: fp32 -> (hi, lo) bf16, streaming
// ---------------------------------------------------------------------------
__global__ void k_split(const float4* __restrict__ src, uint2* __restrict__ hi,
                        uint2* __restrict__ lo, size_t n4) {
    size_t i = (size_t)blockIdx.x * blockDim.x + threadIdx.x;
    if (i >= n4) return;
    uint2 h, l;
    split4(src[i], h, l);
    hi[i] = h; lo[i] = l;
}

// ---------------------------------------------------------------------------
// Gather + split hidden rows into padded [rows, H] bf16 hi/lo
// ---------------------------------------------------------------------------
__global__ void k_prepA(const float* __restrict__ hidden) {
    int idx = blockIdx.x * blockDim.x + threadIdx.x;   // over MAXROWS * 512
    int r  = idx >> 9;
    int c4 = idx & 511;
    if (r >= g_ntiles * TS) return;
    int tok = g_rowtok[r];
    float4 v = (tok >= 0) ? ((const float4*)hidden)[(size_t)tok * 512 + c4]
                          : make_float4(0.f, 0.f, 0.f, 0.f);
    uint2 h, l;
    split4(v, h, l);
    ((uint2*)g_Ah)[(size_t)r * 512 + c4] = h;
    ((uint2*)g_Al)[(size_t)r * 512 + c4] = l;
}

// ---------------------------------------------------------------------------
// SiLU + split
// ---------------------------------------------------------------------------
__global__ void k_silu() {
    int idx = blockIdx.x * blockDim.x + threadIdx.x;   // over MAXROWS * 192
    int r  = idx / 192;
    int c4 = idx - r * 192;
    if (r >= g_ntiles * TS) return;
    const float4* gu = (const float4*)g_gu;
    float4 g = gu[(size_t)r * 384 + c4];
    float4 u = gu[(size_t)r * 384 + 192 + c4];
    float4 h;
    h.x = (g.x / (1.f + expf(-g.x))) * u.x;
    h.y = (g.y / (1.f + expf(-g.y))) * u.y;
    h.z = (g.z / (1.f + expf(-g.z))) * u.z;
    h.w = (g.w / (1.f + expf(-g.w))) * u.w;
    uint2 hh, ll;
    split4(h, hh, ll);
    ((uint2*)g_acth)[(size_t)r * 192 + c4] = hh;
    ((uint2*)g_actl)[(size_t)r * 192 + c4] = ll;
}

// ---------------------------------------------------------------------------
// HMMA grouped GEMM, 64x128 C-tile: C = (Ah+Al) @ (Bh+Bl)^T (3-term bf16x3)
//   256 threads = 8 warps (2m x 4n), warp tile 32x32, BK=32, cp.async x2 buf.
//   Smem rows 80B -> ldmatrix conflict-free.
// ---------------------------------------------------------------------------
#define BUF_A   5120               //  64 rows * 80 B
#define BUF_B   10240              // 128 rows * 80 B
#define OFF_AH  0
#define OFF_AL  BUF_A
#define OFF_BH  (2 * BUF_A)
#define OFF_BL  (2 * BUF_A + BUF_B)
#define STAGE_B (2 * BUF_A + 2 * BUF_B)   // 30720
#define GEMM_SMEM (2 * STAGE_B)           // 61440

template<int NK>   // NK = K / 32
__global__ __launch_bounds__(256) void hmma_gemm(
    const __nv_bfloat16* __restrict__ Ah, const __nv_bfloat16* __restrict__ Al, int lda,
    const __nv_bfloat16* __restrict__ Bh, const __nv_bfloat16* __restrict__ Bl,
    size_t bstride, int ldb, float* __restrict__ C, int ldc)
{
    const int mt = blockIdx.y;
    if (mt >= g_ntiles) return;
    const int e  = g_tile_expert[mt];
    const int n0 = blockIdx.x * 128;

    extern __shared__ char smem[];
    const uint32_t sb = smem_u32(smem);
    const int tid  = threadIdx.x;
    const int wid  = tid >> 5, lane = tid & 31;
    const int wr   = wid >> 2;          // 0..1 (m)
    const int wn   = wid & 3;           // 0..3 (n)

    // A loader: row = tid>>2 (0..63), quarter chunk q = tid&3 (16B each)
    const int arow = tid >> 2, aq = tid & 3;
    const __nv_bfloat16* pAh = Ah + (size_t)(mt * TS + arow) * lda + aq * 8;
    const __nv_bfloat16* pAl = Al + (size_t)(mt * TS + arow) * lda + aq * 8;
    const uint32_t adst = (uint32_t)arow * 80 + (uint32_t)aq * 16;
    // B loader: row = tid>>1 (0..127), 2 chunks cc
    const int brow = tid >> 1, bcc = (tid & 1) * 2;
    const __nv_bfloat16* pBh = Bh + (size_t)e * bstride + (size_t)(n0 + brow) * ldb + bcc * 8;
    const __nv_bfloat16* pBl = Bl + (size_t)e * bstride + (size_t)(n0 + brow) * ldb + bcc * 8;
    const uint32_t bdst = (uint32_t)brow * 80 + (uint32_t)bcc * 16;

#define LOAD_STAGE(s, k0) do {                                                  \
    uint32_t _g = sb + (s) * STAGE_B;                                           \
    CP_ASYNC16(_g + OFF_AH + adst, pAh + (k0));                                 \
    CP_ASYNC16(_g + OFF_AL + adst, pAl + (k0));                                 \
    CP_ASYNC16(_g + OFF_BH + bdst,      pBh + (k0));                            \
    CP_ASYNC16(_g + OFF_BH + bdst + 16, pBh + (k0) + 8);                        \
    CP_ASYNC16(_g + OFF_BL + bdst,      pBl + (k0));                            \
    CP_ASYNC16(_g + OFF_BL + bdst + 16, pBl + (k0) + 8);                        \
    CP_COMMIT();                                                                \
} while (0)

    // ldmatrix lane offsets (within a 16x16 tile base), stride 80B
    const uint32_t aoff = (uint32_t)((((lane >> 3) & 1) * 8 + (lane & 7)) * 80 + (lane >> 4) * 16);
    const uint32_t boff = (uint32_t)(((lane >> 4) * 8 + (lane & 7)) * 80 + ((lane >> 3) & 1) * 16);

    float acc[2][4][4];
#pragma unroll
    for (int i = 0; i < 2; i++)
#pragma unroll
        for (int j = 0; j < 4; j++)
#pragma unroll
            for (int q = 0; q < 4; q++) acc[i][j][q] = 0.f;

    LOAD_STAGE(0, 0);

    for (int kt = 0; kt < NK; kt++) {
        if (kt + 1 < NK) { LOAD_STAGE((kt + 1) & 1, (kt + 1) * 32); CP_WAIT(1); }
        else             { CP_WAIT(0); }
        __syncthreads();

        const uint32_t stg = sb + (kt & 1) * STAGE_B;

#pragma unroll
        for (int kk = 0; kk < 2; kk++) {
            const uint32_t ko = (uint32_t)kk * 32;   // 16 bf16 = 32 bytes
            uint32_t ah[2][4], al[2][4];
#pragma unroll
            for (int i = 0; i < 2; i++) {
                uint32_t ta = (uint32_t)(wr * 32 + i * 16) * 80 + ko;
                LDSM4(ah[i], stg + OFF_AH + ta + aoff);
                LDSM4(al[i], stg + OFF_AL + ta + aoff);
            }
            uint32_t bh[2][4], bl[2][4];
#pragma unroll
            for (int j = 0; j < 2; j++) {
                uint32_t tb = (uint32_t)(wn * 32 + j * 16) * 80 + ko;
                LDSM4(bh[j], stg + OFF_BH + tb + boff);
                LDSM4(bl[j], stg + OFF_BL + tb + boff);
            }
#pragma unroll
            for (int i = 0; i < 2; i++)
#pragma unroll
                for (int j = 0; j < 2; j++)
#pragma unroll
                    for (int s = 0; s < 2; s++) {
                        MMA_BF16(acc[i][j * 2 + s], ah[i], bh[j][2 * s], bh[j][2 * s + 1]);
                        MMA_BF16(acc[i][j * 2 + s], ah[i], bl[j][2 * s], bl[j][2 * s + 1]);
                        MMA_BF16(acc[i][j * 2 + s], al[i], bh[j][2 * s], bh[j][2 * s + 1]);
                    }
        }
        __syncthreads();
    }
#undef LOAD_STAGE

    const int r  = lane >> 2;
    const int c2 = (lane & 3) * 2;
#pragma unroll
    for (int i = 0; i < 2; i++)
#pragma unroll
        for (int j = 0; j < 2; j++)
#pragma unroll
            for (int s = 0; s < 2; s++) {
                float* p = C + (size_t)(mt * TS + wr * 32 + i * 16 + r) * ldc
                             + n0 + wn * 32 + j * 16 + s * 8 + c2;
                p[0] = acc[i][j * 2 + s][0];
                p[1] = acc[i][j * 2 + s][1];
                float* p2 = p + 8 * ldc;
                p2[0] = acc[i][j * 2 + s][2];
                p2[1] = acc[i][j * 2 + s][3];
            }
}

// ---------------------------------------------------------------------------
// Combine: out[t][h] = sum_k tw[t,k] * y2[slot[t,k]][h]
// ---------------------------------------------------------------------------
__global__ void combine_kernel(const float* __restrict__ tw, float* __restrict__ out) {
    int idx = blockIdx.x * blockDim.x + threadIdx.x;
    int t  = idx / (H_DIM / 4);
    int hq = idx - t * (H_DIM / 4);
    if (t >= T_TOK) return;
    float4 acc = make_float4(0.f, 0.f, 0.f, 0.f);
#pragma unroll
    for (int k = 0; k < TOPK; k++) {
        int   s = g_slot[t * TOPK + k];
        float w = tw[t * TOPK + k];
        float4 v = *(const float4*)&g_y2[(size_t)s * H_DIM + hq * 4];
        acc.x += w * v.x; acc.y += w * v.y; acc.z += w * v.z; acc.w += w * v.w;
    }
    *(float4*)&out[(size_t)t * H_DIM + hq * 4] = acc;
}

// ---------------------------------------------------------------------------
extern "C" void kernel_launch(void* const* d_in, const int* in_sizes, int n_in,
                              void* d_out, int out_size) {
    const float* hidden = (const float*)d_in[0];
    const float* tw     = (const float*)d_in[1];
    const int*   ids    = (const int*)d_in[2];
    const float* w1     = (const float*)d_in[3];
    const float* w2     = (const float*)d_in[4];
    float*       out    = (float*)d_out;

    static void *p_w1h, *p_w1l, *p_w2h, *p_w2l, *p_Ah, *p_Al, *p_ah, *p_al, *p_gu, *p_y2;
    cudaGetSymbolAddress(&p_w1h, g_w1h);
    cudaGetSymbolAddress(&p_w1l, g_w1l);
    cudaGetSymbolAddress(&p_w2h, g_w2h);
    cudaGetSymbolAddress(&p_w2l, g_w2l);
    cudaGetSymbolAddress(&p_Ah, g_Ah);
    cudaGetSymbolAddress(&p_Al, g_Al);
    cudaGetSymbolAddress(&p_ah, g_acth);
    cudaGetSymbolAddress(&p_al, g_actl);
    cudaGetSymbolAddress(&p_gu, g_gu);
    cudaGetSymbolAddress(&p_y2, g_y2);

    cudaFuncSetAttribute(hmma_gemm<H_DIM / 32>, cudaFuncAttributeMaxDynamicSharedMemorySize, GEMM_SMEM);
    cudaFuncSetAttribute(hmma_gemm<F_DIM / 32>, cudaFuncAttributeMaxDynamicSharedMemorySize, GEMM_SMEM);

    // side streams for the DRAM-bound weight splits (created once; graph fork/join via events)
    static cudaStream_t s1 = 0, s2 = 0;
    static cudaEvent_t ef1 = 0, ef2 = 0, ew1 = 0, ew2 = 0;
    if (s1 == 0) {
        cudaStreamCreateWithFlags(&s1, cudaStreamNonBlocking);
        cudaStreamCreateWithFlags(&s2, cudaStreamNonBlocking);
        cudaEventCreateWithFlags(&ef1, cudaEventDisableTiming);
        cudaEventCreateWithFlags(&ef2, cudaEventDisableTiming);
        cudaEventCreateWithFlags(&ew1, cudaEventDisableTiming);
        cudaEventCreateWithFlags(&ew2, cudaEventDisableTiming);
    }

    // fork: w1 split on s1, w2 split on s2
    cudaEventRecord(ef1, 0);
    cudaStreamWaitEvent(s1, ef1, 0);
    cudaEventRecord(ef2, 0);
    cudaStreamWaitEvent(s2, ef2, 0);
    {
        size_t n4 = (size_t)NEXP * F2_DIM * H_DIM / 4;
        k_split<<<(unsigned)((n4 + 255) / 256), 256, 0, s1>>>((const float4*)w1, (uint2*)p_w1h, (uint2*)p_w1l, n4);
        cudaEventRecord(ew1, s1);
    }
    {
        size_t n4 = (size_t)NEXP * H_DIM * F_DIM / 4;
        k_split<<<(unsigned)((n4 + 255) / 256), 256, 0, s2>>>((const float4*)w2, (uint2*)p_w2h, (uint2*)p_w2l, n4);
        cudaEventRecord(ew2, s2);
    }

    // main stream: dispatch + activation prep (overlaps with w1 split)
    k_init<<<MAXROWS / 256, 256>>>();
    k_count<<<NPAIR / 256, 256>>>(ids);
    k_scan<<<1, 32>>>();
    k_scatter<<<NEXP, 32>>>(ids);
    k_prepA<<<MAXROWS * 512 / 256, 256>>>(hidden);

    // GEMM1 (needs w1 split)
    cudaStreamWaitEvent(0, ew1, 0);
    hmma_gemm<H_DIM / 32><<<dim3(F2_DIM / 128, MAXTILES), 256, GEMM_SMEM>>>(
        (const __nv_bfloat16*)p_Ah, (const __nv_bfloat16*)p_Al, H_DIM,
        (const __nv_bfloat16*)p_w1h, (const __nv_bfloat16*)p_w1l,
        (size_t)F2_DIM * H_DIM, H_DIM, (float*)p_gu, F2_DIM);

    k_silu<<<MAXROWS * 192 / 256, 256>>>();

    // GEMM2 (needs w2 split — hidden under GEMM1)
    cudaStreamWaitEvent(0, ew2, 0);
    hmma_gemm<F_DIM / 32><<<dim3(H_DIM / 128, MAXTILES), 256, GEMM_SMEM>>>(
        (const __nv_bfloat16*)p_ah, (const __nv_bfloat16*)p_al, F_DIM,
        (const __nv_bfloat16*)p_w2h, (const __nv_bfloat16*)p_w2l,
        (size_t)H_DIM * F_DIM, F_DIM, (float*)p_y2, H_DIM);

    combine_kernel<<<(T_TOK * H_DIM / 4 + 255) / 256, 256>>>(tw, out);
}

// round 11
// speedup vs baseline: 2.5185x; 1.1358x over previous
#include <cuda_runtime.h>
#include <cuda_bf16.h>
#include <cstdint>

// Problem constants: T=1024, H=2048, F=768, E=64, K=8
#define T_TOK   1024
#define H_DIM   2048
#define F_DIM   768
#define F2_DIM  1536
#define NEXP    64
#define TOPK    8
#define NPAIR   (T_TOK * TOPK)
#define TS      64                   // m-tile rows
#define MAXTILES 256                 // worst case: 64 + 8192/64 = 192
#define MAXROWS  16384

// ---------------------------------------------------------------------------
// Device-global scratch (allocation-free per harness rules)
// ---------------------------------------------------------------------------
__device__ int   g_cnt[NEXP];
__device__ int   g_tilebase[NEXP];
__device__ int   g_ntiles;
__device__ int   g_tile_expert[MAXTILES];
__device__ int   g_rowtok[MAXROWS];
__device__ int   g_slot[NPAIR];

__device__ __align__(256) __nv_bfloat16 g_Ah [(size_t)MAXROWS * H_DIM];
__device__ __align__(256) __nv_bfloat16 g_Al [(size_t)MAXROWS * H_DIM];
__device__ __align__(256) __nv_bfloat16 g_acth[(size_t)MAXROWS * F_DIM];
__device__ __align__(256) __nv_bfloat16 g_actl[(size_t)MAXROWS * F_DIM];
__device__ __align__(256) float g_gu [(size_t)MAXROWS * F2_DIM];
__device__ __align__(256) float g_y2 [(size_t)MAXROWS * H_DIM];

// ---------------------------------------------------------------------------
// Portable PTX helpers
// ---------------------------------------------------------------------------
__device__ __forceinline__ uint32_t smem_u32(const void* p) {
    uint32_t a;
    asm("{ .reg .u64 t; cvta.to.shared.u64 t, %1; cvt.u32.u64 %0, t; }" : "=r"(a) : "l"(p));
    return a;
}
#define CP_ASYNC16(dst_u32, src) \
    asm volatile("cp.async.cg.shared.global [%0], [%1], 16;" :: "r"(dst_u32), "l"(src))
#define CP_COMMIT() asm volatile("cp.async.commit_group;" ::: "memory")
#define CP_WAIT(n)  asm volatile("cp.async.wait_group %0;" :: "n"(n) : "memory")

#define LDSM4(r, addr) \
    asm volatile("ldmatrix.sync.aligned.m8n8.x4.shared.b16 {%0,%1,%2,%3}, [%4];" \
        : "=r"((r)[0]), "=r"((r)[1]), "=r"((r)[2]), "=r"((r)[3]) : "r"(addr))

#define MMA_BF16(d, a, b0v, b1v) \
    asm volatile("mma.sync.aligned.m16n8k16.row.col.f32.bf16.bf16.f32 " \
        "{%0,%1,%2,%3}, {%4,%5,%6,%7}, {%8,%9}, {%0,%1,%2,%3};" \
        : "+f"((d)[0]), "+f"((d)[1]), "+f"((d)[2]), "+f"((d)[3]) \
        : "r"((a)[0]), "r"((a)[1]), "r"((a)[2]), "r"((a)[3]), "r"(b0v), "r"(b1v))

#define STSV4(addr, r0, r1, r2, r3) \
    asm volatile("st.shared.v4.b32 [%0], {%1,%2,%3,%4};" \
        :: "r"(addr), "r"(r0), "r"(r1), "r"(r2), "r"(r3) : "memory")

// ---------------------------------------------------------------------------
// bf16 split helpers
// ---------------------------------------------------------------------------
__device__ __forceinline__ uint32_t pk(__nv_bfloat16 a, __nv_bfloat16 b) {
    __nv_bfloat162 t(a, b);
    return *reinterpret_cast<uint32_t*>(&t);
}
__device__ __forceinline__ void split4(float4 v, uint2& hi, uint2& lo) {
    __nv_bfloat16 h0 = __float2bfloat16(v.x), h1 = __float2bfloat16(v.y);
    __nv_bfloat16 h2 = __float2bfloat16(v.z), h3 = __float2bfloat16(v.w);
    __nv_bfloat16 l0 = __float2bfloat16(v.x - __bfloat162float(h0));
    __nv_bfloat16 l1 = __float2bfloat16(v.y - __bfloat162float(h1));
    __nv_bfloat16 l2 = __float2bfloat16(v.z - __bfloat162float(h2));
    __nv_bfloat16 l3 = __float2bfloat16(v.w - __bfloat162float(h3));
    hi = make_uint2(pk(h0, h1), pk(h2, h3));
    lo = make_uint2(pk(l0, l1), pk(l2, l3));
}

// ---------------------------------------------------------------------------
// Dispatch (counting sort, deterministic)
// ---------------------------------------------------------------------------
__global__ void k_init() {
    int i = blockIdx.x * blockDim.x + threadIdx.x;
    if (i < MAXROWS) g_rowtok[i] = -1;
    if (i < NEXP)    g_cnt[i] = 0;
}
__global__ void k_count(const int* __restrict__ ids) {
    int p = blockIdx.x * blockDim.x + threadIdx.x;
    if (p < NPAIR) atomicAdd(&g_cnt[ids[p]], 1);
}
__global__ void k_scan() {
    if (threadIdx.x != 0 || blockIdx.x != 0) return;
    int base = 0;
    for (int e = 0; e < NEXP; e++) {
        g_tilebase[e] = base;
        int nt = (g_cnt[e] + TS - 1) / TS;
        for (int i = 0; i < nt; i++) g_tile_expert[base / TS + i] = e;
        base += nt * TS;
    }
    g_ntiles = base / TS;
}
__global__ void k_scatter(const int* __restrict__ ids) {
    const int e = blockIdx.x, lane = threadIdx.x;
    int off = g_tilebase[e];
    for (int base = 0; base < NPAIR; base += 32) {
        int p = base + lane;
        bool m = (ids[p] == e);
        unsigned mask = __ballot_sync(0xffffffffu, m);
        if (m) {
            int r = off + __popc(mask & ((1u << lane) - 1u));
            g_rowtok[r] = p >> 3;
            g_slot[p] = r;
        }
        off += __popc(mask);
    }
}

// ---------------------------------------------------------------------------
// Gather + split hidden rows into padded [rows, H] bf16 hi/lo
// ---------------------------------------------------------------------------
__global__ void k_prepA(const float* __restrict__ hidden) {
    int idx = blockIdx.x * blockDim.x + threadIdx.x;   // over MAXROWS * 512
    int r  = idx >> 9;
    int c4 = idx & 511;
    if (r >= g_ntiles * TS) return;
    int tok = g_rowtok[r];
    float4 v = (tok >= 0) ? ((const float4*)hidden)[(size_t)tok * 512 + c4]
                          : make_float4(0.f, 0.f, 0.f, 0.f);
    uint2 h, l;
    split4(v, h, l);
    ((uint2*)g_Ah)[(size_t)r * 512 + c4] = h;
    ((uint2*)g_Al)[(size_t)r * 512 + c4] = l;
}

// ---------------------------------------------------------------------------
// SiLU + split
// ---------------------------------------------------------------------------
__global__ void k_silu() {
    int idx = blockIdx.x * blockDim.x + threadIdx.x;   // over MAXROWS * 192
    int r  = idx / 192;
    int c4 = idx - r * 192;
    if (r >= g_ntiles * TS) return;
    const float4* gu = (const float4*)g_gu;
    float4 g = gu[(size_t)r * 384 + c4];
    float4 u = gu[(size_t)r * 384 + 192 + c4];
    float4 h;
    h.x = (g.x / (1.f + expf(-g.x))) * u.x;
    h.y = (g.y / (1.f + expf(-g.y))) * u.y;
    h.z = (g.z / (1.f + expf(-g.z))) * u.z;
    h.w = (g.w / (1.f + expf(-g.w))) * u.w;
    uint2 hh, ll;
    split4(h, hh, ll);
    ((uint2*)g_acth)[(size_t)r * 192 + c4] = hh;
    ((uint2*)g_actl)[(size_t)r * 192 + c4] = ll;
}

// ---------------------------------------------------------------------------
// HMMA grouped GEMM, 64x128 C-tile: C = (Ah+Al) @ (Bh+Bl)^T (3-term bf16x3)
//   B is RAW FP32 (the original weights): loaded via LDG.128 double-buffered
//   in registers, split to hi/lo bf16 in-regs, STS'd into 80B-stride smem.
//   A (activations) is pre-split bf16, cp.async as before.
//   256 threads = 8 warps (2m x 4n), warp tile 32x32, BK=32, 2-stage smem.
// ---------------------------------------------------------------------------
#define BUF_A   5120               //  64 rows * 80 B
#define BUF_B   10240              // 128 rows * 80 B
#define OFF_AH  0
#define OFF_AL  BUF_A
#define OFF_BH  (2 * BUF_A)
#define OFF_BL  (2 * BUF_A + BUF_B)
#define STAGE_B (2 * BUF_A + 2 * BUF_B)   // 30720
#define GEMM_SMEM (2 * STAGE_B)           // 61440

template<int NK>   // NK = K / 32
__global__ __launch_bounds__(256, 2) void hmma_gemm(
    const __nv_bfloat16* __restrict__ Ah, const __nv_bfloat16* __restrict__ Al, int lda,
    const float* __restrict__ B, size_t bstride, int ldb,
    float* __restrict__ C, int ldc)
{
    const int mt = blockIdx.y;
    if (mt >= g_ntiles) return;
    const int e  = g_tile_expert[mt];
    const int n0 = blockIdx.x * 128;

    extern __shared__ char smem[];
    const uint32_t sb = smem_u32(smem);
    const int tid  = threadIdx.x;
    const int wid  = tid >> 5, lane = tid & 31;
    const int wr   = wid >> 2;          // 0..1 (m)
    const int wn   = wid & 3;           // 0..3 (n)

    // A loader: row = tid>>2 (0..63), 16B chunk q = tid&3
    const int arow = tid >> 2, aq = tid & 3;
    const __nv_bfloat16* pAh = Ah + (size_t)(mt * TS + arow) * lda + aq * 8;
    const __nv_bfloat16* pAl = Al + (size_t)(mt * TS + arow) * lda + aq * 8;
    const uint32_t adst = (uint32_t)arow * 80 + (uint32_t)aq * 16;
    // B loader (fp32): row = tid>>1 (0..127), half = tid&1 covers 16 floats
    const int brow = tid >> 1, bhalf = tid & 1;
    const float* pB = B + (size_t)e * bstride + (size_t)(n0 + brow) * ldb + bhalf * 16;
    const uint32_t bdst = (uint32_t)brow * 80 + (uint32_t)bhalf * 32;

#define LOAD_A(s, k0) do {                                                      \
    uint32_t _g = sb + (s) * STAGE_B;                                           \
    CP_ASYNC16(_g + OFF_AH + adst, pAh + (k0));                                 \
    CP_ASYNC16(_g + OFF_AL + adst, pAl + (k0));                                 \
    CP_COMMIT();                                                                \
} while (0)

#define LOAD_B(dst, k0) do {                                                    \
    float4 _t0 = *(const float4*)(pB + (k0));                                   \
    float4 _t1 = *(const float4*)(pB + (k0) + 4);                               \
    float4 _t2 = *(const float4*)(pB + (k0) + 8);                               \
    float4 _t3 = *(const float4*)(pB + (k0) + 12);                              \
    dst[0]=_t0.x; dst[1]=_t0.y; dst[2]=_t0.z; dst[3]=_t0.w;                     \
    dst[4]=_t1.x; dst[5]=_t1.y; dst[6]=_t1.z; dst[7]=_t1.w;                     \
    dst[8]=_t2.x; dst[9]=_t2.y; dst[10]=_t2.z; dst[11]=_t2.w;                   \
    dst[12]=_t3.x; dst[13]=_t3.y; dst[14]=_t3.z; dst[15]=_t3.w;                 \
} while (0)

#define CONV_STS(s, bv) do {                                                    \
    uint32_t _g = sb + (s) * STAGE_B;                                           \
    uint32_t _hb[8], _lb[8];                                                    \
    _Pragma("unroll")                                                           \
    for (int _i = 0; _i < 8; _i++) {                                            \
        float _x = bv[2 * _i], _y = bv[2 * _i + 1];                             \
        __nv_bfloat16 _hx = __float2bfloat16(_x), _hy = __float2bfloat16(_y);   \
        _hb[_i] = pk(_hx, _hy);                                                 \
        _lb[_i] = pk(__float2bfloat16(_x - __bfloat162float(_hx)),              \
                     __float2bfloat16(_y - __bfloat162float(_hy)));             \
    }                                                                           \
    STSV4(_g + OFF_BH + bdst,      _hb[0], _hb[1], _hb[2], _hb[3]);             \
    STSV4(_g + OFF_BH + bdst + 16, _hb[4], _hb[5], _hb[6], _hb[7]);             \
    STSV4(_g + OFF_BL + bdst,      _lb[0], _lb[1], _lb[2], _lb[3]);             \
    STSV4(_g + OFF_BL + bdst + 16, _lb[4], _lb[5], _lb[6], _lb[7]);             \
} while (0)

    // ldmatrix lane offsets (within a 16x16 tile base), stride 80B
    const uint32_t aoff = (uint32_t)((((lane >> 3) & 1) * 8 + (lane & 7)) * 80 + (lane >> 4) * 16);
    const uint32_t boff = (uint32_t)(((lane >> 4) * 8 + (lane & 7)) * 80 + ((lane >> 3) & 1) * 16);

    float acc[2][4][4];
#pragma unroll
    for (int i = 0; i < 2; i++)
#pragma unroll
        for (int j = 0; j < 4; j++)
#pragma unroll
            for (int q = 0; q < 4; q++) acc[i][j][q] = 0.f;

    float bcur[16], bnxt[16];
    LOAD_B(bcur, 0);
    LOAD_A(0, 0);

    for (int kt = 0; kt < NK; kt++) {
        const int s = kt & 1;
        if (kt + 1 < NK) {
            LOAD_B(bnxt, (kt + 1) * 32);
            LOAD_A((kt + 1) & 1, (kt + 1) * 32);
            CP_WAIT(1);
        } else {
            CP_WAIT(0);
        }
        CONV_STS(s, bcur);
        __syncthreads();

        const uint32_t stg = sb + s * STAGE_B;
#pragma unroll
        for (int kk = 0; kk < 2; kk++) {
            const uint32_t ko = (uint32_t)kk * 32;
            uint32_t ah[2][4], al[2][4];
#pragma unroll
            for (int i = 0; i < 2; i++) {
                uint32_t ta = (uint32_t)(wr * 32 + i * 16) * 80 + ko;
                LDSM4(ah[i], stg + OFF_AH + ta + aoff);
                LDSM4(al[i], stg + OFF_AL + ta + aoff);
            }
            uint32_t bh[2][4], bl[2][4];
#pragma unroll
            for (int j = 0; j < 2; j++) {
                uint32_t tb = (uint32_t)(wn * 32 + j * 16) * 80 + ko;
                LDSM4(bh[j], stg + OFF_BH + tb + boff);
                LDSM4(bl[j], stg + OFF_BL + tb + boff);
            }
#pragma unroll
            for (int i = 0; i < 2; i++)
#pragma unroll
                for (int j = 0; j < 2; j++)
#pragma unroll
                    for (int s2 = 0; s2 < 2; s2++) {
                        MMA_BF16(acc[i][j * 2 + s2], ah[i], bh[j][2 * s2], bh[j][2 * s2 + 1]);
                        MMA_BF16(acc[i][j * 2 + s2], ah[i], bl[j][2 * s2], bl[j][2 * s2 + 1]);
                        MMA_BF16(acc[i][j * 2 + s2], al[i], bh[j][2 * s2], bh[j][2 * s2 + 1]);
                    }
        }
        __syncthreads();
#pragma unroll
        for (int i = 0; i < 16; i++) bcur[i] = bnxt[i];
    }
#undef LOAD_A
#undef LOAD_B
#undef CONV_STS

    const int r  = lane >> 2;
    const int c2 = (lane & 3) * 2;
#pragma unroll
    for (int i = 0; i < 2; i++)
#pragma unroll
        for (int j = 0; j < 2; j++)
#pragma unroll
            for (int s2 = 0; s2 < 2; s2++) {
                float* p = C + (size_t)(mt * TS + wr * 32 + i * 16 + r) * ldc
                             + n0 + wn * 32 + j * 16 + s2 * 8 + c2;
                p[0] = acc[i][j * 2 + s2][0];
                p[1] = acc[i][j * 2 + s2][1];
                float* p2 = p + 8 * ldc;
                p2[0] = acc[i][j * 2 + s2][2];
                p2[1] = acc[i][j * 2 + s2][3];
            }
}

// ---------------------------------------------------------------------------
// Combine: out[t][h] = sum_k tw[t,k] * y2[slot[t,k]][h]
// ---------------------------------------------------------------------------
__global__ void combine_kernel(const float* __restrict__ tw, float* __restrict__ out) {
    int idx = blockIdx.x * blockDim.x + threadIdx.x;
    int t  = idx / (H_DIM / 4);
    int hq = idx - t * (H_DIM / 4);
    if (t >= T_TOK) return;
    float4 acc = make_float4(0.f, 0.f, 0.f, 0.f);
#pragma unroll
    for (int k = 0; k < TOPK; k++) {
        int   s = g_slot[t * TOPK + k];
        float w = tw[t * TOPK + k];
        float4 v = *(const float4*)&g_y2[(size_t)s * H_DIM + hq * 4];
        acc.x += w * v.x; acc.y += w * v.y; acc.z += w * v.z; acc.w += w * v.w;
    }
    *(float4*)&out[(size_t)t * H_DIM + hq * 4] = acc;
}

// ---------------------------------------------------------------------------
extern "C" void kernel_launch(void* const* d_in, const int* in_sizes, int n_in,
                              void* d_out, int out_size) {
    const float* hidden = (const float*)d_in[0];
    const float* tw     = (const float*)d_in[1];
    const int*   ids    = (const int*)d_in[2];
    const float* w1     = (const float*)d_in[3];
    const float* w2     = (const float*)d_in[4];
    float*       out    = (float*)d_out;

    static void *p_Ah, *p_Al, *p_ah, *p_al, *p_gu, *p_y2;
    cudaGetSymbolAddress(&p_Ah, g_Ah);
    cudaGetSymbolAddress(&p_Al, g_Al);
    cudaGetSymbolAddress(&p_ah, g_acth);
    cudaGetSymbolAddress(&p_al, g_actl);
    cudaGetSymbolAddress(&p_gu, g_gu);
    cudaGetSymbolAddress(&p_y2, g_y2);

    cudaFuncSetAttribute(hmma_gemm<H_DIM / 32>, cudaFuncAttributeMaxDynamicSharedMemorySize, GEMM_SMEM);
    cudaFuncSetAttribute(hmma_gemm<F_DIM / 32>, cudaFuncAttributeMaxDynamicSharedMemorySize, GEMM_SMEM);

    // dispatch + activation prep
    k_init<<<MAXROWS / 256, 256>>>();
    k_count<<<NPAIR / 256, 256>>>(ids);
    k_scan<<<1, 32>>>();
    k_scatter<<<NEXP, 32>>>(ids);
    k_prepA<<<MAXROWS * 512 / 256, 256>>>(hidden);

    // GEMM1: gu = A @ w1^T  (K = 2048; B = raw fp32 w1, split in-kernel)
    hmma_gemm<H_DIM / 32><<<dim3(F2_DIM / 128, MAXTILES), 256, GEMM_SMEM>>>(
        (const __nv_bfloat16*)p_Ah, (const __nv_bfloat16*)p_Al, H_DIM,
        w1, (size_t)F2_DIM * H_DIM, H_DIM, (float*)p_gu, F2_DIM);

    k_silu<<<MAXROWS * 192 / 256, 256>>>();

    // GEMM2: y2 = act @ w2^T  (K = 768; B = raw fp32 w2, split in-kernel)
    hmma_gemm<F_DIM / 32><<<dim3(H_DIM / 128, MAXTILES), 256, GEMM_SMEM>>>(
        (const __nv_bfloat16*)p_ah, (const __nv_bfloat16*)p_al, F_DIM,
        w2, (size_t)H_DIM * F_DIM, F_DIM, (float*)p_y2, H_DIM);

    combine_kernel<<<(T_TOK * H_DIM / 4 + 255) / 256, 256>>>(tw, out);
}